// round 6
// baseline (speedup 1.0000x reference)
#include <cuda_runtime.h>
#include <cuda_fp16.h>
#include <cstdint>

// SparseLinear: out[8192,128] = coo(ids, vals, 8192x8192) @ x[8192,128]
// v6: DENSE path. W densified to fp16 (128MB), scatter = atomicAdd(half),
//     then a tensor-core (mma.sync m16n8k16) GEMM with cp.async pipeline.
// Launches: init (detect + zero out + x^T fp16) -> zero_w -> scatter -> gemm.

#define N_DIM   8192
#define B_COLS  128

__device__ int    g_is64;
__device__ __half g_w[N_DIM * (size_t)N_DIM];   // dense W, fp16, 128 MB
__device__ __half g_xt[B_COLS * N_DIM];         // x^T fp16 [128][8192], 2 MB

// ---------------------------------------------------------------------------
// 1) init: detect id dtype (block 0), zero out, build x^T in fp16.
// ---------------------------------------------------------------------------
__global__ void init_kernel(const int* __restrict__ ids32,
                            const float* __restrict__ x,
                            float* __restrict__ out) {
    int tid    = blockIdx.x * blockDim.x + threadIdx.x;
    int stride = gridDim.x * blockDim.x;

    // int64 ids with values < 8192 have all-zero odd 32-bit words.
    if (blockIdx.x == 0) {
        __shared__ int s_bad;
        if (threadIdx.x == 0) s_bad = 0;
        __syncthreads();
        int bad = 0;
        for (int i = threadIdx.x; i < 2048; i += blockDim.x)
            if (ids32[2 * i + 1] != 0) bad = 1;
        if (bad) atomicOr(&s_bad, 1);
        __syncthreads();
        if (threadIdx.x == 0) g_is64 = s_bad ? 0 : 1;
    }

    // zero out (gemm accumulates with atomicAdd)
    for (int i = tid; i < N_DIM * B_COLS; i += stride) out[i] = 0.f;

    // x^T: unit = (n, k0/4): read x[k0+j][n] (coalesced across lanes),
    // write 4 halves to g_xt[n][k0..k0+3].
    for (int u = tid; u < B_COLS * (N_DIM / 4); u += stride) {
        int n  = u & (B_COLS - 1);
        int k0 = (u >> 7) * 4;
        float f0 = x[(k0 + 0) * B_COLS + n];
        float f1 = x[(k0 + 1) * B_COLS + n];
        float f2 = x[(k0 + 2) * B_COLS + n];
        float f3 = x[(k0 + 3) * B_COLS + n];
        __half2* dst = reinterpret_cast<__half2*>(&g_xt[n * N_DIM + k0]);
        dst[0] = __floats2half2_rn(f0, f1);
        dst[1] = __floats2half2_rn(f2, f3);
    }
}

// ---------------------------------------------------------------------------
// 2) zero W: 128 MB of STG.128.
// ---------------------------------------------------------------------------
__global__ void zero_w_kernel() {
    uint4* p = reinterpret_cast<uint4*>(g_w);
    size_t n = (size_t)N_DIM * N_DIM / 8;       // 8 halves per uint4
    size_t stride = (size_t)gridDim.x * blockDim.x;
    uint4 z = make_uint4(0u, 0u, 0u, 0u);
    for (size_t i = (size_t)blockIdx.x * blockDim.x + threadIdx.x; i < n;
         i += stride)
        p[i] = z;
}

// ---------------------------------------------------------------------------
// 3) scatter: W[row][col] += val via RED.ADD.F16 (duplicates sum, as COO
//    coalesce requires). Addresses spread over 64M cells -> no serialization.
// ---------------------------------------------------------------------------
__global__ void scatter_kernel(const int* __restrict__ ids32,
                               const float* __restrict__ vals, int nnz) {
    const int is64 = g_is64;
    int stride = gridDim.x * blockDim.x;
    for (int e = blockIdx.x * blockDim.x + threadIdx.x; e < nnz; e += stride) {
        int row, col;
        if (is64) {
            row = ids32[2 * e];
            col = ids32[2 * (nnz + e)];
        } else {
            row = ids32[e];
            col = ids32[nnz + e];
        }
        atomicAdd(&g_w[(size_t)row * N_DIM + col], __float2half_rn(vals[e]));
    }
}

// ---------------------------------------------------------------------------
// 4) GEMM: out = W @ x.  CTA tile 128(M) x 128(N), 8 warps of 32x64,
//    K split in 2 (grid 128). Per iter: K-chunk of 64 halves; W tile and
//    x^T tile staged via cp.async into padded smem (144B rows -> ldmatrix
//    conflict-free). mma.sync.m16n8k16 f16*f16 -> f32. Epilogue: RED.F32.
// ---------------------------------------------------------------------------
#define TILE_BYTES 18432          // 128 rows * 144B (64 halves + 16B pad)
#define KB         64             // K halves per iter
#define KSPLIT     2
#define NIT        (N_DIM / KSPLIT / KB)   // 64

__device__ __forceinline__ void cp16(void* dst, const void* src) {
    unsigned sa = (unsigned)__cvta_generic_to_shared(dst);
    asm volatile("cp.async.cg.shared.global [%0], [%1], 16;\n"
                 :: "r"(sa), "l"(src));
}

__device__ __forceinline__ void ldsm4(uint32_t& r0, uint32_t& r1,
                                      uint32_t& r2, uint32_t& r3,
                                      const void* p) {
    unsigned sa = (unsigned)__cvta_generic_to_shared(p);
    asm volatile("ldmatrix.sync.aligned.m8n8.x4.shared.b16 "
                 "{%0,%1,%2,%3}, [%4];"
                 : "=r"(r0), "=r"(r1), "=r"(r2), "=r"(r3) : "r"(sa));
}

__device__ __forceinline__ void mma16816(float c[4],
                                         uint32_t a0, uint32_t a1,
                                         uint32_t a2, uint32_t a3,
                                         uint32_t b0, uint32_t b1) {
    asm volatile("mma.sync.aligned.m16n8k16.row.col.f32.f16.f16.f32 "
                 "{%0,%1,%2,%3}, {%4,%5,%6,%7}, {%8,%9}, {%0,%1,%2,%3};"
                 : "+f"(c[0]), "+f"(c[1]), "+f"(c[2]), "+f"(c[3])
                 : "r"(a0), "r"(a1), "r"(a2), "r"(a3), "r"(b0), "r"(b1));
}

__global__ void __launch_bounds__(256, 1)
gemm_kernel(float* __restrict__ out) {
    extern __shared__ char sm[];
    char* wbuf[2] = { sm,               sm + TILE_BYTES };
    char* xbuf[2] = { sm + 2*TILE_BYTES, sm + 3*TILE_BYTES };

    int mt = blockIdx.x >> 1;                 // 0..63
    int ks = blockIdx.x & 1;                  // k split
    int m0 = mt * 128;
    int kbase = ks * (N_DIM / KSPLIT);        // halves

    int t    = threadIdx.x;
    int w    = t >> 5;
    int lane = t & 31;
    int wm   = w >> 1;                        // 0..3, 32-row slab
    int wn   = w & 1;                         // 0..1, 64-col slab

    // fill(kb): 1024 W chunks + 1024 x^T chunks of 16B; 4 each per thread
    int fr = t >> 3;          // base row (adds +32 per i)
    int fc = t & 7;           // 16B chunk within row
    const __half* wsrc0 = g_w  + (size_t)(m0 + fr) * N_DIM + kbase + fc * 8;
    const __half* xsrc0 = g_xt + (size_t)fr * N_DIM        + kbase + fc * 8;

#define FILL(kb)                                                             \
    {                                                                        \
        int koff = (kb) * KB;                                                \
        char* wd = wbuf[(kb) & 1] + fr * 144 + fc * 16;                      \
        char* xd = xbuf[(kb) & 1] + fr * 144 + fc * 16;                      \
        _Pragma("unroll")                                                    \
        for (int i = 0; i < 4; i++) {                                        \
            cp16(wd + i * 32 * 144, wsrc0 + (size_t)i * 32 * N_DIM + koff);  \
            cp16(xd + i * 32 * 144, xsrc0 + (size_t)i * 32 * N_DIM + koff);  \
        }                                                                    \
        asm volatile("cp.async.commit_group;\n");                            \
    }

    float c[2][8][4];
    #pragma unroll
    for (int i = 0; i < 2; i++)
        #pragma unroll
        for (int j = 0; j < 8; j++)
            #pragma unroll
            for (int k = 0; k < 4; k++) c[i][j][k] = 0.f;

    // ldmatrix lane addressing (within tile, bytes)
    int arow  = wm * 32 + (lane & 15);
    int acol  = (lane >> 4) * 16;
    int brow  = wn * 64 + ((lane >> 4) << 3) + (lane & 7);
    int bcol  = ((lane >> 3) & 1) * 16;

    FILL(0);

    for (int kb = 0; kb < NIT; kb++) {
        if (kb + 1 < NIT) {
            FILL(kb + 1);
            asm volatile("cp.async.wait_group 1;\n");
        } else {
            asm volatile("cp.async.wait_group 0;\n");
        }
        __syncthreads();

        const char* wb = wbuf[kb & 1];
        const char* xb = xbuf[kb & 1];

        #pragma unroll
        for (int ksub = 0; ksub < 4; ksub++) {
            uint32_t a[2][4];
            #pragma unroll
            for (int mf = 0; mf < 2; mf++)
                ldsm4(a[mf][0], a[mf][1], a[mf][2], a[mf][3],
                      wb + (arow + 16 * mf) * 144 + ksub * 32 + acol);
            #pragma unroll
            for (int nb = 0; nb < 4; nb++) {
                uint32_t b0, b1, b2, b3;
                ldsm4(b0, b1, b2, b3,
                      xb + (brow + nb * 16) * 144 + ksub * 32 + bcol);
                mma16816(c[0][2*nb],   a[0][0],a[0][1],a[0][2],a[0][3], b0,b1);
                mma16816(c[0][2*nb+1], a[0][0],a[0][1],a[0][2],a[0][3], b2,b3);
                mma16816(c[1][2*nb],   a[1][0],a[1][1],a[1][2],a[1][3], b0,b1);
                mma16816(c[1][2*nb+1], a[1][0],a[1][1],a[1][2],a[1][3], b2,b3);
            }
        }
        __syncthreads();
    }

    // epilogue: RED.F32 into out (both K-splits accumulate; out zeroed in init)
    int g  = lane >> 2;
    int t2 = (lane & 3) * 2;
    #pragma unroll
    for (int mf = 0; mf < 2; mf++) {
        #pragma unroll
        for (int ni = 0; ni < 8; ni++) {
            float* p = out + (size_t)(m0 + wm * 32 + 16 * mf + g) * B_COLS
                           + wn * 64 + ni * 8 + t2;
            atomicAdd(p,     c[mf][ni][0]);
            atomicAdd(p + 1, c[mf][ni][1]);
            float* q = p + 8 * B_COLS;
            atomicAdd(q,     c[mf][ni][2]);
            atomicAdd(q + 1, c[mf][ni][3]);
        }
    }
#undef FILL
}

// ---------------------------------------------------------------------------
// Launch
// ---------------------------------------------------------------------------
extern "C" void kernel_launch(void* const* d_in, const int* in_sizes, int n_in,
                              void* d_out, int out_size) {
    const int*   ids32 = (const int*)d_in[0];    // int64 or int32 (detected)
    const float* vals  = (const float*)d_in[1];  // [nnz]
    const float* x     = (const float*)d_in[2];  // [8192, 128] fp32
    float*       out   = (float*)d_out;          // [8192, 128] fp32

    int nnz = in_sizes[1];

    cudaFuncSetAttribute(gemm_kernel,
                         cudaFuncAttributeMaxDynamicSharedMemorySize,
                         4 * TILE_BYTES);

    init_kernel<<<592, 256>>>(ids32, x, out);
    zero_w_kernel<<<1184, 256>>>();
    scatter_kernel<<<1184, 256>>>(ids32, vals, nnz);
    gemm_kernel<<<128, 256, 4 * TILE_BYTES>>>(out);
}

// round 7
// speedup vs baseline: 1.0029x; 1.0029x over previous
#include <cuda_runtime.h>
#include <cuda_fp16.h>
#include <cstdint>

// SparseLinear: out[8192,128] = coo(ids, vals, 8192x8192) @ x[8192,128]
// v6: DENSE path. W densified to fp16 (128MB), scatter = atomicAdd(half),
//     then a tensor-core (mma.sync m16n8k16) GEMM with cp.async pipeline.
// Launches: init (detect + zero out + x^T fp16) -> zero_w -> scatter -> gemm.

#define N_DIM   8192
#define B_COLS  128

__device__ int    g_is64;
__device__ __half g_w[N_DIM * (size_t)N_DIM];   // dense W, fp16, 128 MB
__device__ __half g_xt[B_COLS * N_DIM];         // x^T fp16 [128][8192], 2 MB

// ---------------------------------------------------------------------------
// 1) init: detect id dtype (block 0), zero out, build x^T in fp16.
// ---------------------------------------------------------------------------
__global__ void init_kernel(const int* __restrict__ ids32,
                            const float* __restrict__ x,
                            float* __restrict__ out) {
    int tid    = blockIdx.x * blockDim.x + threadIdx.x;
    int stride = gridDim.x * blockDim.x;

    // int64 ids with values < 8192 have all-zero odd 32-bit words.
    if (blockIdx.x == 0) {
        __shared__ int s_bad;
        if (threadIdx.x == 0) s_bad = 0;
        __syncthreads();
        int bad = 0;
        for (int i = threadIdx.x; i < 2048; i += blockDim.x)
            if (ids32[2 * i + 1] != 0) bad = 1;
        if (bad) atomicOr(&s_bad, 1);
        __syncthreads();
        if (threadIdx.x == 0) g_is64 = s_bad ? 0 : 1;
    }

    // zero out (gemm accumulates with atomicAdd)
    for (int i = tid; i < N_DIM * B_COLS; i += stride) out[i] = 0.f;

    // x^T: unit = (n, k0/4): read x[k0+j][n] (coalesced across lanes),
    // write 4 halves to g_xt[n][k0..k0+3].
    for (int u = tid; u < B_COLS * (N_DIM / 4); u += stride) {
        int n  = u & (B_COLS - 1);
        int k0 = (u >> 7) * 4;
        float f0 = x[(k0 + 0) * B_COLS + n];
        float f1 = x[(k0 + 1) * B_COLS + n];
        float f2 = x[(k0 + 2) * B_COLS + n];
        float f3 = x[(k0 + 3) * B_COLS + n];
        __half2* dst = reinterpret_cast<__half2*>(&g_xt[n * N_DIM + k0]);
        dst[0] = __floats2half2_rn(f0, f1);
        dst[1] = __floats2half2_rn(f2, f3);
    }
}

// ---------------------------------------------------------------------------
// 2) zero W: 128 MB of STG.128.
// ---------------------------------------------------------------------------
__global__ void zero_w_kernel() {
    uint4* p = reinterpret_cast<uint4*>(g_w);
    size_t n = (size_t)N_DIM * N_DIM / 8;       // 8 halves per uint4
    size_t stride = (size_t)gridDim.x * blockDim.x;
    uint4 z = make_uint4(0u, 0u, 0u, 0u);
    for (size_t i = (size_t)blockIdx.x * blockDim.x + threadIdx.x; i < n;
         i += stride)
        p[i] = z;
}

// ---------------------------------------------------------------------------
// 3) scatter: W[row][col] += val via RED.ADD.F16 (duplicates sum, as COO
//    coalesce requires). Addresses spread over 64M cells -> no serialization.
// ---------------------------------------------------------------------------
__global__ void scatter_kernel(const int* __restrict__ ids32,
                               const float* __restrict__ vals, int nnz) {
    const int is64 = g_is64;
    int stride = gridDim.x * blockDim.x;
    for (int e = blockIdx.x * blockDim.x + threadIdx.x; e < nnz; e += stride) {
        int row, col;
        if (is64) {
            row = ids32[2 * e];
            col = ids32[2 * (nnz + e)];
        } else {
            row = ids32[e];
            col = ids32[nnz + e];
        }
        atomicAdd(&g_w[(size_t)row * N_DIM + col], __float2half_rn(vals[e]));
    }
}

// ---------------------------------------------------------------------------
// 4) GEMM: out = W @ x.  CTA tile 128(M) x 128(N), 8 warps of 32x64,
//    K split in 2 (grid 128). Per iter: K-chunk of 64 halves; W tile and
//    x^T tile staged via cp.async into padded smem (144B rows -> ldmatrix
//    conflict-free). mma.sync.m16n8k16 f16*f16 -> f32. Epilogue: RED.F32.
// ---------------------------------------------------------------------------
#define TILE_BYTES 18432          // 128 rows * 144B (64 halves + 16B pad)
#define KB         64             // K halves per iter
#define KSPLIT     2
#define NIT        (N_DIM / KSPLIT / KB)   // 64

__device__ __forceinline__ void cp16(void* dst, const void* src) {
    unsigned sa = (unsigned)__cvta_generic_to_shared(dst);
    asm volatile("cp.async.cg.shared.global [%0], [%1], 16;\n"
                 :: "r"(sa), "l"(src));
}

__device__ __forceinline__ void ldsm4(uint32_t& r0, uint32_t& r1,
                                      uint32_t& r2, uint32_t& r3,
                                      const void* p) {
    unsigned sa = (unsigned)__cvta_generic_to_shared(p);
    asm volatile("ldmatrix.sync.aligned.m8n8.x4.shared.b16 "
                 "{%0,%1,%2,%3}, [%4];"
                 : "=r"(r0), "=r"(r1), "=r"(r2), "=r"(r3) : "r"(sa));
}

__device__ __forceinline__ void mma16816(float c[4],
                                         uint32_t a0, uint32_t a1,
                                         uint32_t a2, uint32_t a3,
                                         uint32_t b0, uint32_t b1) {
    asm volatile("mma.sync.aligned.m16n8k16.row.col.f32.f16.f16.f32 "
                 "{%0,%1,%2,%3}, {%4,%5,%6,%7}, {%8,%9}, {%0,%1,%2,%3};"
                 : "+f"(c[0]), "+f"(c[1]), "+f"(c[2]), "+f"(c[3])
                 : "r"(a0), "r"(a1), "r"(a2), "r"(a3), "r"(b0), "r"(b1));
}

__global__ void __launch_bounds__(256, 1)
gemm_kernel(float* __restrict__ out) {
    extern __shared__ char sm[];
    char* wbuf[2] = { sm,               sm + TILE_BYTES };
    char* xbuf[2] = { sm + 2*TILE_BYTES, sm + 3*TILE_BYTES };

    int mt = blockIdx.x >> 1;                 // 0..63
    int ks = blockIdx.x & 1;                  // k split
    int m0 = mt * 128;
    int kbase = ks * (N_DIM / KSPLIT);        // halves

    int t    = threadIdx.x;
    int w    = t >> 5;
    int lane = t & 31;
    int wm   = w >> 1;                        // 0..3, 32-row slab
    int wn   = w & 1;                         // 0..1, 64-col slab

    // fill(kb): 1024 W chunks + 1024 x^T chunks of 16B; 4 each per thread
    int fr = t >> 3;          // base row (adds +32 per i)
    int fc = t & 7;           // 16B chunk within row
    const __half* wsrc0 = g_w  + (size_t)(m0 + fr) * N_DIM + kbase + fc * 8;
    const __half* xsrc0 = g_xt + (size_t)fr * N_DIM        + kbase + fc * 8;

#define FILL(kb)                                                             \
    {                                                                        \
        int koff = (kb) * KB;                                                \
        char* wd = wbuf[(kb) & 1] + fr * 144 + fc * 16;                      \
        char* xd = xbuf[(kb) & 1] + fr * 144 + fc * 16;                      \
        _Pragma("unroll")                                                    \
        for (int i = 0; i < 4; i++) {                                        \
            cp16(wd + i * 32 * 144, wsrc0 + (size_t)i * 32 * N_DIM + koff);  \
            cp16(xd + i * 32 * 144, xsrc0 + (size_t)i * 32 * N_DIM + koff);  \
        }                                                                    \
        asm volatile("cp.async.commit_group;\n");                            \
    }

    float c[2][8][4];
    #pragma unroll
    for (int i = 0; i < 2; i++)
        #pragma unroll
        for (int j = 0; j < 8; j++)
            #pragma unroll
            for (int k = 0; k < 4; k++) c[i][j][k] = 0.f;

    // ldmatrix lane addressing (within tile, bytes)
    int arow  = wm * 32 + (lane & 15);
    int acol  = (lane >> 4) * 16;
    int brow  = wn * 64 + ((lane >> 4) << 3) + (lane & 7);
    int bcol  = ((lane >> 3) & 1) * 16;

    FILL(0);

    for (int kb = 0; kb < NIT; kb++) {
        if (kb + 1 < NIT) {
            FILL(kb + 1);
            asm volatile("cp.async.wait_group 1;\n");
        } else {
            asm volatile("cp.async.wait_group 0;\n");
        }
        __syncthreads();

        const char* wb = wbuf[kb & 1];
        const char* xb = xbuf[kb & 1];

        #pragma unroll
        for (int ksub = 0; ksub < 4; ksub++) {
            uint32_t a[2][4];
            #pragma unroll
            for (int mf = 0; mf < 2; mf++)
                ldsm4(a[mf][0], a[mf][1], a[mf][2], a[mf][3],
                      wb + (arow + 16 * mf) * 144 + ksub * 32 + acol);
            #pragma unroll
            for (int nb = 0; nb < 4; nb++) {
                uint32_t b0, b1, b2, b3;
                ldsm4(b0, b1, b2, b3,
                      xb + (brow + nb * 16) * 144 + ksub * 32 + bcol);
                mma16816(c[0][2*nb],   a[0][0],a[0][1],a[0][2],a[0][3], b0,b1);
                mma16816(c[0][2*nb+1], a[0][0],a[0][1],a[0][2],a[0][3], b2,b3);
                mma16816(c[1][2*nb],   a[1][0],a[1][1],a[1][2],a[1][3], b0,b1);
                mma16816(c[1][2*nb+1], a[1][0],a[1][1],a[1][2],a[1][3], b2,b3);
            }
        }
        __syncthreads();
    }

    // epilogue: RED.F32 into out (both K-splits accumulate; out zeroed in init)
    int g  = lane >> 2;
    int t2 = (lane & 3) * 2;
    #pragma unroll
    for (int mf = 0; mf < 2; mf++) {
        #pragma unroll
        for (int ni = 0; ni < 8; ni++) {
            float* p = out + (size_t)(m0 + wm * 32 + 16 * mf + g) * B_COLS
                           + wn * 64 + ni * 8 + t2;
            atomicAdd(p,     c[mf][ni][0]);
            atomicAdd(p + 1, c[mf][ni][1]);
            float* q = p + 8 * B_COLS;
            atomicAdd(q,     c[mf][ni][2]);
            atomicAdd(q + 1, c[mf][ni][3]);
        }
    }
#undef FILL
}

// ---------------------------------------------------------------------------
// Launch
// ---------------------------------------------------------------------------
extern "C" void kernel_launch(void* const* d_in, const int* in_sizes, int n_in,
                              void* d_out, int out_size) {
    const int*   ids32 = (const int*)d_in[0];    // int64 or int32 (detected)
    const float* vals  = (const float*)d_in[1];  // [nnz]
    const float* x     = (const float*)d_in[2];  // [8192, 128] fp32
    float*       out   = (float*)d_out;          // [8192, 128] fp32

    int nnz = in_sizes[1];

    cudaFuncSetAttribute(gemm_kernel,
                         cudaFuncAttributeMaxDynamicSharedMemorySize,
                         4 * TILE_BYTES);

    init_kernel<<<592, 256>>>(ids32, x, out);
    zero_w_kernel<<<1184, 256>>>();
    scatter_kernel<<<1184, 256>>>(ids32, vals, nnz);
    gemm_kernel<<<128, 256, 4 * TILE_BYTES>>>(out);
}

// round 8
// speedup vs baseline: 1.5291x; 1.5247x over previous
#include <cuda_runtime.h>
#include <cuda_fp16.h>
#include <cstdint>

// SparseLinear: out[8192,128] = coo(ids, vals, 8192x8192) @ x[8192,128]
// v8: smem-chunked SpMM, fixed: triple-buffered fills (1 sync/chunk),
//     transposed [row][chunk] bucket counts loaded once, pack words
//     prefetched one chunk ahead into registers.
// Launches: detect -> init -> scatter -> spmm  (spmm is 4th => profiled).

#define N_ROWS      8192
#define N_CHUNK     32
#define CHUNK_COLS  256
#define CHUNK_BYTES (CHUNK_COLS * 256)      // 65536: 256 x-rows of 256B fp16
#define CAP         32                      // mean 8 entries/bucket
#define OVER_CAP    65536
#define R_PER_BLK   64
#define N_BLOCKS    (N_ROWS / R_PER_BLK)    // 128

__device__ int      g_is64;
__device__ int      g_bcnt[N_ROWS * N_CHUNK];          // [row][chunk], 1 MB
__device__ int      g_over_cnt;
__device__ uint2    g_over[OVER_CAP];                  // (row, val<<16|col)
__device__ unsigned g_bpack[N_ROWS * N_CHUNK * CAP];   // [row][chunk][slot] 32MB
__device__ __half2  g_xh[N_ROWS * 64];                 // x fp16, 2 MB

// ---------------------------------------------------------------------------
// 0) detect id dtype: int64 ids < 8192 have all-zero odd 32-bit words.
// ---------------------------------------------------------------------------
__global__ void detect_kernel(const int* __restrict__ ids32) {
    __shared__ int s_bad;
    if (threadIdx.x == 0) s_bad = 0;
    __syncthreads();
    int bad = 0;
    for (int i = threadIdx.x; i < 2048; i += blockDim.x)
        if (ids32[2 * i + 1] != 0) bad = 1;
    if (bad) atomicOr(&s_bad, 1);
    __syncthreads();
    if (threadIdx.x == 0) g_is64 = s_bad ? 0 : 1;
}

// ---------------------------------------------------------------------------
// 1) init: zero bucket counters, convert x -> fp16.
// ---------------------------------------------------------------------------
__global__ void init_kernel(const float* __restrict__ x) {
    int tid    = blockIdx.x * blockDim.x + threadIdx.x;
    int stride = gridDim.x * blockDim.x;

    for (int i = tid; i < N_ROWS * N_CHUNK; i += stride) g_bcnt[i] = 0;
    if (tid == 0) g_over_cnt = 0;

    const float4* __restrict__ x4 = reinterpret_cast<const float4*>(x);
    for (int i = tid; i < N_ROWS * 32; i += stride) {
        float4 v = x4[i];
        g_xh[2 * i]     = __floats2half2_rn(v.x, v.y);
        g_xh[2 * i + 1] = __floats2half2_rn(v.z, v.w);
    }
}

// ---------------------------------------------------------------------------
// 2) scatter into (row, chunk) buckets; 4-byte packed (fp16 val | colOff).
// ---------------------------------------------------------------------------
__device__ __forceinline__ void scatter_one(int row, int col, float v) {
    unsigned vh = (unsigned)__half_as_ushort(__float2half_rn(v));
    int      b  = row * N_CHUNK + (col >> 8);
    int p = atomicAdd(&g_bcnt[b], 1);
    if (p < CAP) {
        g_bpack[b * CAP + p] = (vh << 16) | (unsigned)(col & 0xFF);
    } else {
        int q = atomicAdd(&g_over_cnt, 1);
        if (q < OVER_CAP)
            g_over[q] = make_uint2((unsigned)row, (vh << 16) | (unsigned)col);
    }
}

__global__ void scatter_kernel(const int* __restrict__ ids32,
                               const float* __restrict__ vals, int nnz) {
    const int is64 = g_is64;
    int stride = gridDim.x * blockDim.x;
    for (int e = blockIdx.x * blockDim.x + threadIdx.x; e < nnz; e += stride) {
        int row, col;
        if (is64) {
            row = ids32[2 * e];
            col = ids32[2 * (nnz + e)];
        } else {
            row = ids32[e];
            col = ids32[nnz + e];
        }
        scatter_one(row, col, vals[e]);
    }
}

// ---------------------------------------------------------------------------
// 3) spmm: 128 CTAs x 1024 thr, CTA owns 64 rows (warp w -> rows r0+w,
//    r0+w+32). 32 chunks; x chunk (64KB) triple-buffered via cp.async,
//    ONE syncthreads per chunk. Chunk-count vectors preloaded per row;
//    pack words prefetched one chunk ahead. Lane l owns cols [4l,4l+4).
// ---------------------------------------------------------------------------
__global__ void __launch_bounds__(1024, 1)
spmm_kernel(float* __restrict__ out) {
    extern __shared__ unsigned char s_x[];   // 3 * 64KB
    int r0   = blockIdx.x * R_PER_BLK;
    int w    = threadIdx.x >> 5;
    int lane = threadIdx.x & 31;
    int rA   = r0 + w;
    int rB   = r0 + w + 32;

    // fill addressing: 64 B per thread per chunk (4 x 16B cp.async)
    const unsigned char* xsrc = reinterpret_cast<const unsigned char*>(g_xh);
    int foff = threadIdx.x * 64;

#define FILL(c)                                                              \
    {                                                                        \
        unsigned char* d = s_x + ((c) % 3) * CHUNK_BYTES + foff;             \
        const unsigned char* s = xsrc + (size_t)(c) * CHUNK_BYTES + foff;    \
        unsigned sa = (unsigned)__cvta_generic_to_shared(d);                 \
        asm volatile("cp.async.cg.shared.global [%0], [%1], 16;\n"           \
                     :: "r"(sa), "l"(s));                                    \
        asm volatile("cp.async.cg.shared.global [%0], [%1], 16;\n"           \
                     :: "r"(sa + 16), "l"(s + 16));                          \
        asm volatile("cp.async.cg.shared.global [%0], [%1], 16;\n"           \
                     :: "r"(sa + 32), "l"(s + 32));                          \
        asm volatile("cp.async.cg.shared.global [%0], [%1], 16;\n"           \
                     :: "r"(sa + 48), "l"(s + 48));                          \
        asm volatile("cp.async.commit_group;\n");                            \
    }

    // per-row chunk-count vectors: lane l holds count of chunk l (one load).
    int cntA = __ldg(&g_bcnt[rA * N_CHUNK + lane]);
    int cntB = __ldg(&g_bcnt[rB * N_CHUNK + lane]);

    // prefetch pack words for chunk 0
    int ccA = __shfl_sync(0xffffffffu, cntA, 0); if (ccA > CAP) ccA = CAP;
    int ccB = __shfl_sync(0xffffffffu, cntB, 0); if (ccB > CAP) ccB = CAP;
    unsigned pA_n = 0u, pB_n = 0u;
    if (lane < ccA) pA_n = __ldg(&g_bpack[(rA * N_CHUNK) * CAP + lane]);
    if (lane < ccB) pB_n = __ldg(&g_bpack[(rB * N_CHUNK) * CAP + lane]);
    int cA_n = ccA, cB_n = ccB;

    FILL(0);

    float4 accA = make_float4(0.f, 0.f, 0.f, 0.f);
    float4 accB = make_float4(0.f, 0.f, 0.f, 0.f);

    for (int c = 0; c < N_CHUNK; c++) {
        // rotate prefetched entries into current
        unsigned pA = pA_n, pB = pB_n;
        int      cA = cA_n, cB = cB_n;

        if (c + 1 < N_CHUNK) {
            FILL(c + 1);   // writes buf[(c+1)%3]; last read ended 2 chunks ago
            // prefetch next chunk's pack words (L2 latency hidden by compute)
            int nA = __shfl_sync(0xffffffffu, cntA, c + 1);
            int nB = __shfl_sync(0xffffffffu, cntB, c + 1);
            if (nA > CAP) nA = CAP;
            if (nB > CAP) nB = CAP;
            pA_n = 0u; pB_n = 0u;
            if (lane < nA)
                pA_n = __ldg(&g_bpack[(rA * N_CHUNK + c + 1) * CAP + lane]);
            if (lane < nB)
                pB_n = __ldg(&g_bpack[(rB * N_CHUNK + c + 1) * CAP + lane]);
            cA_n = nA; cB_n = nB;
            asm volatile("cp.async.wait_group 1;\n");
        } else {
            asm volatile("cp.async.wait_group 0;\n");
        }
        __syncthreads();   // fill(c) visible to all; joins compute(c-1)

        const unsigned char* buf = s_x + (c % 3) * CHUNK_BYTES + lane * 8;

        #pragma unroll 4
        for (int j = 0; j < cA; j++) {
            unsigned pj = __shfl_sync(0xffffffffu, pA, j);
            float    vj = __half2float(__ushort_as_half(
                              (unsigned short)(pj >> 16)));
            uint2 xr = *reinterpret_cast<const uint2*>(buf + (pj & 0xFFu) * 256);
            float2 f0 = __half22float2(*reinterpret_cast<__half2*>(&xr.x));
            float2 f1 = __half22float2(*reinterpret_cast<__half2*>(&xr.y));
            accA.x += vj * f0.x;  accA.y += vj * f0.y;
            accA.z += vj * f1.x;  accA.w += vj * f1.y;
        }
        #pragma unroll 4
        for (int j = 0; j < cB; j++) {
            unsigned pj = __shfl_sync(0xffffffffu, pB, j);
            float    vj = __half2float(__ushort_as_half(
                              (unsigned short)(pj >> 16)));
            uint2 xr = *reinterpret_cast<const uint2*>(buf + (pj & 0xFFu) * 256);
            float2 f0 = __half22float2(*reinterpret_cast<__half2*>(&xr.x));
            float2 f1 = __half22float2(*reinterpret_cast<__half2*>(&xr.y));
            accB.x += vj * f0.x;  accB.y += vj * f0.y;
            accB.z += vj * f1.x;  accB.w += vj * f1.y;
        }
    }

    // overflow entries (normally zero).
    int nov = g_over_cnt;
    if (nov > OVER_CAP) nov = OVER_CAP;
    const uint2* __restrict__ xg = reinterpret_cast<const uint2*>(g_xh);
    for (int q = 0; q < nov; q++) {
        uint2 o  = __ldg(&g_over[q]);
        int   dr = (int)o.x - r0;
        if (dr >= 0 && dr < R_PER_BLK && (dr & 31) == w) {
            float    vj  = __half2float(__ushort_as_half(
                              (unsigned short)(o.y >> 16)));
            unsigned col = o.y & 0xFFFFu;
            uint2 xr = __ldg(&xg[col * 32 + lane]);
            float2 f0 = __half22float2(*reinterpret_cast<__half2*>(&xr.x));
            float2 f1 = __half22float2(*reinterpret_cast<__half2*>(&xr.y));
            if (dr < 32) {
                accA.x += vj * f0.x;  accA.y += vj * f0.y;
                accA.z += vj * f1.x;  accA.w += vj * f1.y;
            } else {
                accB.x += vj * f0.x;  accB.y += vj * f0.y;
                accB.z += vj * f1.x;  accB.w += vj * f1.y;
            }
        }
    }

    float4* __restrict__ o4 = reinterpret_cast<float4*>(out);
    o4[rA * 32 + lane] = accA;
    o4[rB * 32 + lane] = accB;
#undef FILL
}

// ---------------------------------------------------------------------------
// Launch — spmm is the 4th launch (the one ncu samples).
// ---------------------------------------------------------------------------
extern "C" void kernel_launch(void* const* d_in, const int* in_sizes, int n_in,
                              void* d_out, int out_size) {
    const int*   ids32 = (const int*)d_in[0];    // int64 or int32 (detected)
    const float* vals  = (const float*)d_in[1];  // [nnz]
    const float* x     = (const float*)d_in[2];  // [8192, 128] fp32
    float*       out   = (float*)d_out;          // [8192, 128] fp32

    int nnz = in_sizes[1];

    cudaFuncSetAttribute(spmm_kernel,
                         cudaFuncAttributeMaxDynamicSharedMemorySize,
                         3 * CHUNK_BYTES);

    detect_kernel<<<1, 256>>>(ids32);
    init_kernel<<<592, 256>>>(x);
    scatter_kernel<<<1184, 256>>>(ids32, vals, nnz);
    spmm_kernel<<<N_BLOCKS, 1024, 3 * CHUNK_BYTES>>>(out);
}